// round 1
// baseline (speedup 1.0000x reference)
#include <cuda_runtime.h>
#include <math.h>

#define N_NODES 100000
#define F_IN    512
#define F_H     256
#define F_C     40

// -------- scratch (no cudaMalloc allowed) --------
__device__ float g_h1  [(size_t)N_NODES * F_H];   // x @ W1
__device__ float g_agg1[(size_t)N_NODES * F_H];   // aggregated + relu'd
__device__ float g_h2  [(size_t)N_NODES * F_C];   // relu(h) @ W2
__device__ float g_agg2[(size_t)N_NODES * F_C];
__device__ float g_deg [N_NODES];
__device__ float g_dinv[N_NODES];
__device__ int   g_is64;

// -------- edge dtype probe (int64 vs int32-canonicalized) --------
__global__ void detect_dtype(const void* edges) {
    if (threadIdx.x == 0 && blockIdx.x == 0) {
        const long long* p = (const long long*)edges;
        int ok = 1;
        for (int i = 0; i < 64; i++) {
            long long v = p[i];
            if (v < 0 || v >= N_NODES) ok = 0;
        }
        g_is64 = ok;   // int32 pairs reinterpreted as int64 are >= 2^32 (w.h.p.)
    }
}

__device__ __forceinline__ long long edge_at(const void* edges, long long idx) {
    if (g_is64) return ((const long long*)edges)[idx];
    return (long long)((const int*)edges)[idx];
}

// -------- degree / dinv --------
__global__ void init_deg(int n) {
    int i = blockIdx.x * blockDim.x + threadIdx.x;
    if (i < n) g_deg[i] = 1.0f;               // self-loop
}
__global__ void count_deg(const void* edges, long long E) {
    long long e = (long long)blockIdx.x * blockDim.x + threadIdx.x;
    if (e >= E) return;
    long long dst = edge_at(edges, E + e);
    atomicAdd(&g_deg[dst], 1.0f);
}
__global__ void compute_dinv(int n) {
    int i = blockIdx.x * blockDim.x + threadIdx.x;
    if (i < n) g_dinv[i] = rsqrtf(g_deg[i]);
}

// -------- zero scratch --------
__global__ void zero_agg1() {
    long long i = (long long)blockIdx.x * blockDim.x + threadIdx.x;
    long long n4 = (long long)N_NODES * F_H / 4;
    if (i < n4) ((float4*)g_agg1)[i] = make_float4(0.f, 0.f, 0.f, 0.f);
}
__global__ void zero_agg2() {
    long long i = (long long)blockIdx.x * blockDim.x + threadIdx.x;
    long long n4 = (long long)N_NODES * F_C / 4;
    if (i < n4) ((float4*)g_agg2)[i] = make_float4(0.f, 0.f, 0.f, 0.f);
}

// -------- GEMM1: h1[M,256] = x[M,512] @ W1[512,256] --------
// BM=128 BN=64 BK=16, 8x8 per thread, 128 threads.
__global__ __launch_bounds__(128) void gemm1(const float* __restrict__ A,
                                             const float* __restrict__ B,
                                             int M) {
    __shared__ float As[16][132];   // padded: conflict-free transposed stores
    __shared__ float Bs[16][64];

    int tid = threadIdx.x;
    int m0 = blockIdx.x * 128;
    int n0 = blockIdx.y * 64;
    int ty = tid >> 3;      // 0..15 -> row group
    int tx = tid & 7;       // 0..7  -> col group

    float acc[8][8];
#pragma unroll
    for (int r = 0; r < 8; r++)
#pragma unroll
        for (int c = 0; c < 8; c++) acc[r][c] = 0.f;

    for (int k0 = 0; k0 < F_IN; k0 += 16) {
        // load A tile 128x16 (transposed into smem)
#pragma unroll
        for (int i = 0; i < 4; i++) {
            int idx = tid + i * 128;           // 0..511
            int ar = idx >> 2;                 // 0..127
            int ac4 = idx & 3;                 // 0..3
            int gr = m0 + ar;
            float4 v = make_float4(0.f, 0.f, 0.f, 0.f);
            if (gr < M) v = *(const float4*)&A[(size_t)gr * F_IN + k0 + ac4 * 4];
            As[ac4 * 4 + 0][ar] = v.x;
            As[ac4 * 4 + 1][ar] = v.y;
            As[ac4 * 4 + 2][ar] = v.z;
            As[ac4 * 4 + 3][ar] = v.w;
        }
        // load B tile 16x64
#pragma unroll
        for (int i = 0; i < 2; i++) {
            int idx = tid + i * 128;           // 0..255
            int br = idx >> 4;                 // 0..15
            int bc4 = idx & 15;                // 0..15
            float4 v = *(const float4*)&B[(size_t)(k0 + br) * F_H + n0 + bc4 * 4];
            *(float4*)&Bs[br][bc4 * 4] = v;
        }
        __syncthreads();

#pragma unroll
        for (int k = 0; k < 16; k++) {
            float ra[8], rb[8];
#pragma unroll
            for (int r = 0; r < 8; r++) ra[r] = As[k][ty * 8 + r];
#pragma unroll
            for (int c = 0; c < 8; c++) rb[c] = Bs[k][tx * 8 + c];
#pragma unroll
            for (int r = 0; r < 8; r++)
#pragma unroll
                for (int c = 0; c < 8; c++) acc[r][c] = fmaf(ra[r], rb[c], acc[r][c]);
        }
        __syncthreads();
    }

#pragma unroll
    for (int r = 0; r < 8; r++) {
        int gr = m0 + ty * 8 + r;
        if (gr < M) {
#pragma unroll
            for (int c4 = 0; c4 < 2; c4++) {
                float4 v = make_float4(acc[r][c4 * 4 + 0], acc[r][c4 * 4 + 1],
                                       acc[r][c4 * 4 + 2], acc[r][c4 * 4 + 3]);
                *(float4*)&g_h1[(size_t)gr * F_H + n0 + tx * 8 + c4 * 4] = v;
            }
        }
    }
}

// -------- scatter layer 1: agg1[dst] += h1[src] * dinv[src]*dinv[dst] --------
// warp per edge, vectorized red.global.add.v4.f32
__global__ void scatter1(const void* __restrict__ edges, long long E) {
    long long gid = (long long)blockIdx.x * blockDim.x + threadIdx.x;
    long long e = gid >> 5;
    int lane = threadIdx.x & 31;
    if (e >= E) return;
    long long src = edge_at(edges, e);
    long long dst = edge_at(edges, E + e);
    float w = g_dinv[src] * g_dinv[dst];
    const float4* hs = (const float4*)&g_h1[(size_t)src * F_H];
    float4* od = (float4*)&g_agg1[(size_t)dst * F_H];
#pragma unroll
    for (int i = 0; i < 2; i++) {
        int c = lane + i * 32;     // 0..63 float4 chunks
        float4 v = hs[c];
        v.x *= w; v.y *= w; v.z *= w; v.w *= w;
        asm volatile("red.global.add.v4.f32 [%0], {%1,%2,%3,%4};"
                     :: "l"(od + c), "f"(v.x), "f"(v.y), "f"(v.z), "f"(v.w)
                     : "memory");
    }
}

// -------- post1: agg1 = relu(agg1 + h1*dinv^2 + b1) --------
__global__ void post1(const float* __restrict__ b1, int M) {
    long long gid = (long long)blockIdx.x * blockDim.x + threadIdx.x;
    long long total = (long long)M * (F_H / 4);
    if (gid >= total) return;
    int i  = (int)(gid >> 6);       // node
    int c4 = (int)(gid & 63);       // float4 chunk
    float w = g_dinv[i]; w *= w;
    float4 a = ((const float4*)g_agg1)[gid];
    float4 h = ((const float4*)g_h1)[gid];
    float4 bb = ((const float4*)b1)[c4];
    a.x = fmaxf(fmaf(h.x, w, a.x) + bb.x, 0.f);
    a.y = fmaxf(fmaf(h.y, w, a.y) + bb.y, 0.f);
    a.z = fmaxf(fmaf(h.z, w, a.z) + bb.z, 0.f);
    a.w = fmaxf(fmaf(h.w, w, a.w) + bb.w, 0.f);
    ((float4*)g_agg1)[gid] = a;
}

// -------- GEMM2: h2[M,40] = agg1[M,256] @ W2[256,40] --------
__global__ __launch_bounds__(256) void gemm2(const float* __restrict__ W2, int M) {
    __shared__ float W2s[F_H * F_C];   // 40 KB
    for (int i = threadIdx.x; i < F_H * F_C / 4; i += 256)
        ((float4*)W2s)[i] = ((const float4*)W2)[i];
    __syncthreads();

    int row = blockIdx.x * blockDim.x + threadIdx.x;
    if (row >= M) return;

    float4 acc[10];
#pragma unroll
    for (int c = 0; c < 10; c++) acc[c] = make_float4(0.f, 0.f, 0.f, 0.f);

    const float4* hr = (const float4*)&g_agg1[(size_t)row * F_H];
    for (int k4 = 0; k4 < F_H / 4; k4++) {
        float4 h = hr[k4];
        float hv[4] = {h.x, h.y, h.z, h.w};
#pragma unroll
        for (int kk = 0; kk < 4; kk++) {
            const float4* wrow = (const float4*)&W2s[(k4 * 4 + kk) * F_C];
#pragma unroll
            for (int c = 0; c < 10; c++) {
                float4 wv = wrow[c];
                acc[c].x = fmaf(hv[kk], wv.x, acc[c].x);
                acc[c].y = fmaf(hv[kk], wv.y, acc[c].y);
                acc[c].z = fmaf(hv[kk], wv.z, acc[c].z);
                acc[c].w = fmaf(hv[kk], wv.w, acc[c].w);
            }
        }
    }
    float4* out = (float4*)&g_h2[(size_t)row * F_C];
#pragma unroll
    for (int c = 0; c < 10; c++) out[c] = acc[c];
}

// -------- scatter layer 2: agg2[dst] += h2[src] * norm  (40 feats) --------
__global__ void scatter2(const void* __restrict__ edges, long long E) {
    long long gid = (long long)blockIdx.x * blockDim.x + threadIdx.x;
    long long e = gid / 10;
    int c = (int)(gid - e * 10);
    if (e >= E) return;
    long long src = edge_at(edges, e);
    long long dst = edge_at(edges, E + e);
    float w = g_dinv[src] * g_dinv[dst];
    float4 v = ((const float4*)&g_h2[(size_t)src * F_C])[c];
    v.x *= w; v.y *= w; v.z *= w; v.w *= w;
    float4* od = (float4*)&g_agg2[(size_t)dst * F_C];
    asm volatile("red.global.add.v4.f32 [%0], {%1,%2,%3,%4};"
                 :: "l"(od + c), "f"(v.x), "f"(v.y), "f"(v.z), "f"(v.w)
                 : "memory");
}

// -------- final: out = log_softmax(agg2 + h2*dinv^2 + b2) --------
__global__ void final_k(const float* __restrict__ b2, float* __restrict__ out, int M) {
    int i = blockIdx.x * blockDim.x + threadIdx.x;
    if (i >= M) return;
    float w = g_dinv[i]; w *= w;
    float v[F_C];
    const float4* a4 = (const float4*)&g_agg2[(size_t)i * F_C];
    const float4* h4 = (const float4*)&g_h2[(size_t)i * F_C];
    const float4* bb = (const float4*)b2;
#pragma unroll
    for (int c = 0; c < 10; c++) {
        float4 a = a4[c], h = h4[c], b = bb[c];
        v[c * 4 + 0] = fmaf(h.x, w, a.x) + b.x;
        v[c * 4 + 1] = fmaf(h.y, w, a.y) + b.y;
        v[c * 4 + 2] = fmaf(h.z, w, a.z) + b.z;
        v[c * 4 + 3] = fmaf(h.w, w, a.w) + b.w;
    }
    float mx = v[0];
#pragma unroll
    for (int c = 1; c < F_C; c++) mx = fmaxf(mx, v[c]);
    float s = 0.f;
#pragma unroll
    for (int c = 0; c < F_C; c++) s += expf(v[c] - mx);
    float ls = mx + logf(s);
    float4* o = (float4*)&out[(size_t)i * F_C];
#pragma unroll
    for (int c = 0; c < 10; c++) {
        float4 r;
        r.x = v[c * 4 + 0] - ls;
        r.y = v[c * 4 + 1] - ls;
        r.z = v[c * 4 + 2] - ls;
        r.w = v[c * 4 + 3] - ls;
        o[c] = r;
    }
}

extern "C" void kernel_launch(void* const* d_in, const int* in_sizes, int n_in,
                              void* d_out, int out_size) {
    const float* x  = (const float*)d_in[0];
    const float* W1 = (const float*)d_in[1];
    const float* b1 = (const float*)d_in[2];
    const float* W2 = (const float*)d_in[3];
    const float* b2 = (const float*)d_in[4];
    const void*  ei = d_in[5];

    int M = in_sizes[0] / F_IN;                 // 100000
    long long E = (long long)in_sizes[5] / 2;   // 3.2M

    detect_dtype<<<1, 32>>>(ei);

    init_deg<<<(M + 255) / 256, 256>>>(M);
    count_deg<<<(int)((E + 255) / 256), 256>>>(ei, E);
    compute_dinv<<<(M + 255) / 256, 256>>>(M);

    gemm1<<<dim3((M + 127) / 128, F_H / 64), 128>>>(x, W1, M);

    {
        long long n4 = (long long)N_NODES * F_H / 4;
        zero_agg1<<<(int)((n4 + 255) / 256), 256>>>();
    }
    scatter1<<<(int)((E * 32 + 255) / 256), 256>>>(ei, E);
    {
        long long total = (long long)M * (F_H / 4);
        post1<<<(int)((total + 255) / 256), 256>>>(b1, M);
    }

    gemm2<<<(M + 255) / 256, 256>>>(W2, M);

    {
        long long n4 = (long long)N_NODES * F_C / 4;
        zero_agg2<<<(int)((n4 + 255) / 256), 256>>>();
    }
    scatter2<<<(int)((E * 10 + 255) / 256), 256>>>(ei, E);

    final_k<<<(M + 255) / 256, 256>>>(b2, (float*)d_out, M);
}

// round 3
// speedup vs baseline: 2.2153x; 2.2153x over previous
#include <cuda_runtime.h>
#include <cuda_bf16.h>
#include <math.h>
#include <stdint.h>

#define N_NODES 100000
#define F_IN    512
#define F_H     256
#define F_C     40
#define E_MAX   3200000

// ================= scratch (__device__ globals; no cudaMalloc) =================
__device__ float          g_h1  [(size_t)N_NODES * F_H];
__device__ float          g_agg1[(size_t)N_NODES * F_H];
__device__ float          g_h2  [(size_t)N_NODES * F_C];
__device__ __nv_bfloat16  g_xhi [(size_t)N_NODES * F_IN];
__device__ __nv_bfloat16  g_xlo [(size_t)N_NODES * F_IN];
__device__ __nv_bfloat16  g_wthi[(size_t)F_H * F_IN];    // W1^T hi  [256][512]
__device__ __nv_bfloat16  g_wtlo[(size_t)F_H * F_IN];
__device__ float          g_dinv[N_NODES];
__device__ int            g_cnt [N_NODES];
__device__ int            g_rowp[N_NODES];
__device__ int            g_curs[N_NODES];
__device__ int            g_col [E_MAX];
__device__ int            g_bsum[512];
__device__ int            g_boff[512];
__device__ int            g_is64;

__device__ __forceinline__ uint32_t smem_u32(const void* p) {
    uint32_t a;
    asm("{ .reg .u64 t; cvta.to.shared.u64 t, %1; cvt.u32.u64 %0, t; }" : "=r"(a) : "l"(p));
    return a;
}

// ================= edge dtype probe =================
__global__ void detect_dtype(const void* edges) {
    if (threadIdx.x == 0 && blockIdx.x == 0) {
        const long long* p = (const long long*)edges;
        int ok = 1;
        for (int i = 0; i < 64; i++) {
            long long v = p[i];
            if (v < 0 || v >= N_NODES) ok = 0;
        }
        g_is64 = ok;
    }
}
__device__ __forceinline__ int edge_at(const void* edges, long long idx) {
    if (g_is64) return (int)((const long long*)edges)[idx];
    return ((const int*)edges)[idx];
}

// ================= CSR build =================
__global__ void zero_cnt(int n) {
    int i = blockIdx.x * blockDim.x + threadIdx.x;
    if (i < n) g_cnt[i] = 0;
}
__global__ void hist(const void* edges, long long E) {
    long long e = (long long)blockIdx.x * blockDim.x + threadIdx.x;
    if (e >= E) return;
    atomicAdd(&g_cnt[edge_at(edges, E + e)], 1);
}
__global__ void scan1(int n) {
    __shared__ int sh[256];
    int i = blockIdx.x * 256 + threadIdx.x;
    int v = (i < n) ? g_cnt[i] : 0;
    sh[threadIdx.x] = v;
    __syncthreads();
#pragma unroll
    for (int off = 1; off < 256; off <<= 1) {
        int t = (threadIdx.x >= off) ? sh[threadIdx.x - off] : 0;
        __syncthreads();
        sh[threadIdx.x] += t;
        __syncthreads();
    }
    if (i < n) g_rowp[i] = sh[threadIdx.x] - v;
    if (threadIdx.x == 255) g_bsum[blockIdx.x] = sh[255];
}
__global__ void scan2(int nb) {
    __shared__ int sh[512];
    int v = (threadIdx.x < nb) ? g_bsum[threadIdx.x] : 0;
    sh[threadIdx.x] = v;
    __syncthreads();
#pragma unroll
    for (int off = 1; off < 512; off <<= 1) {
        int t = (threadIdx.x >= off) ? sh[threadIdx.x - off] : 0;
        __syncthreads();
        sh[threadIdx.x] += t;
        __syncthreads();
    }
    g_boff[threadIdx.x] = sh[threadIdx.x] - v;
}
__global__ void scan3(int n) {
    int i = blockIdx.x * blockDim.x + threadIdx.x;
    if (i >= n) return;
    int rp = g_rowp[i] + g_boff[i >> 8];
    g_rowp[i] = rp;
    g_curs[i] = rp;
    g_dinv[i] = rsqrtf((float)(g_cnt[i] + 1));
}
__global__ void fill_csr(const void* edges, long long E) {
    long long e = (long long)blockIdx.x * blockDim.x + threadIdx.x;
    if (e >= E) return;
    int src = edge_at(edges, e);
    int dst = edge_at(edges, E + e);
    int pos = atomicAdd(&g_curs[dst], 1);
    g_col[pos] = src;
}

// ================= bf16 splits =================
__global__ void split_x(const float* __restrict__ x, long long n4) {
    long long g = (long long)blockIdx.x * blockDim.x + threadIdx.x;
    if (g >= n4) return;
    float4 v = ((const float4*)x)[g];
    __nv_bfloat16 h0 = __float2bfloat16_rn(v.x), h1 = __float2bfloat16_rn(v.y);
    __nv_bfloat16 h2 = __float2bfloat16_rn(v.z), h3 = __float2bfloat16_rn(v.w);
    __nv_bfloat16 l0 = __float2bfloat16_rn(v.x - __bfloat162float(h0));
    __nv_bfloat16 l1 = __float2bfloat16_rn(v.y - __bfloat162float(h1));
    __nv_bfloat16 l2 = __float2bfloat16_rn(v.z - __bfloat162float(h2));
    __nv_bfloat16 l3 = __float2bfloat16_rn(v.w - __bfloat162float(h3));
    __nv_bfloat162* ph = (__nv_bfloat162*)g_xhi;
    __nv_bfloat162* pl = (__nv_bfloat162*)g_xlo;
    ph[g * 2]     = __nv_bfloat162(h0, h1);
    ph[g * 2 + 1] = __nv_bfloat162(h2, h3);
    pl[g * 2]     = __nv_bfloat162(l0, l1);
    pl[g * 2 + 1] = __nv_bfloat162(l2, l3);
}
__global__ void split_w(const float* __restrict__ W1) {
    int idx = blockIdx.x * blockDim.x + threadIdx.x;   // over 512*256
    if (idx >= F_IN * F_H) return;
    int k = idx / F_H, n = idx % F_H;
    float v = W1[idx];
    __nv_bfloat16 h = __float2bfloat16_rn(v);
    __nv_bfloat16 l = __float2bfloat16_rn(v - __bfloat162float(h));
    g_wthi[(size_t)n * F_IN + k] = h;
    g_wtlo[(size_t)n * F_IN + k] = l;
}

// ================= GEMM1 via mma.sync (HMMA, bf16 split) =================
// Tile: BM=128, BN=128, BK=32. 256 threads = 8 warps (4 M x 2 N).
// smem rows padded to 40 bf16 (80B) -> ldmatrix conflict-free.
#define SST_B     80                       // smem row stride in bytes
#define TILE_B    (128 * SST_B)            // 10240 bytes per variant tile
#define STAGE_B   (4 * TILE_B)             // Ahi|Alo|Bhi|Blo = 40960
#define GEMM1_SMEM (2 * STAGE_B)           // 81920

#define LDMX4(r, a)                                                              \
    asm volatile("ldmatrix.sync.aligned.m8n8.x4.shared.b16 {%0,%1,%2,%3}, [%4];" \
                 : "=r"((r)[0]), "=r"((r)[1]), "=r"((r)[2]), "=r"((r)[3])        \
                 : "r"(a))

#define MMA16816(d, a, b0, b1)                                                   \
    asm volatile("mma.sync.aligned.m16n8k16.row.col.f32.bf16.bf16.f32 "          \
                 "{%0,%1,%2,%3}, {%4,%5,%6,%7}, {%8,%9}, {%0,%1,%2,%3};"         \
                 : "+f"((d)[0]), "+f"((d)[1]), "+f"((d)[2]), "+f"((d)[3])        \
                 : "r"((a)[0]), "r"((a)[1]), "r"((a)[2]), "r"((a)[3]),           \
                   "r"(b0), "r"(b1))

#define CPA16(sa, ga, sz)                                                        \
    asm volatile("cp.async.cg.shared.global [%0], [%1], 16, %2;"                 \
                 :: "r"(sa), "l"(ga), "r"(sz))
#define CPA16F(sa, ga)                                                           \
    asm volatile("cp.async.cg.shared.global [%0], [%1], 16;" :: "r"(sa), "l"(ga))
#define CP_COMMIT() asm volatile("cp.async.commit_group;" ::: "memory")
#define CP_WAIT(n)  asm volatile("cp.async.wait_group %0;" :: "n"(n) : "memory")

__device__ __forceinline__ void g1_load_stage(uint32_t smb, uint32_t stg,
                                              int m0, int n0g, int k0, int M, int tid) {
#pragma unroll
    for (int it = 0; it < 2; it++) {
        int c = tid + it * 256;            // 0..511
        int row = c >> 2, q = c & 3;
        int grow = m0 + row;
        int sz = (grow < M) ? 16 : 0;
        int gr = (grow < M) ? grow : 0;
        size_t go = (size_t)gr * F_IN + k0 + q * 8;
        uint32_t sa = smb + stg + row * SST_B + q * 16;
        CPA16(sa, &g_xhi[go], sz);
        CPA16(sa + TILE_B, &g_xlo[go], sz);
    }
#pragma unroll
    for (int it = 0; it < 2; it++) {
        int c = tid + it * 256;
        int row = c >> 2, q = c & 3;       // row = n 0..127
        size_t go = (size_t)(n0g + row) * F_IN + k0 + q * 8;
        uint32_t sa = smb + stg + 2 * TILE_B + row * SST_B + q * 16;
        CPA16F(sa, &g_wthi[go]);
        CPA16F(sa + TILE_B, &g_wtlo[go]);
    }
}

__global__ void __launch_bounds__(256) gemm1_mma(int M) {
    extern __shared__ char sm[];
    uint32_t smb = smem_u32(sm);
    int tid = threadIdx.x;
    int lane = tid & 31, wid = tid >> 5;
    int mwarp = wid & 3, nwarp = wid >> 2;
    int m0 = blockIdx.x * 128, n0g = blockIdx.y * 128;

    float acc[2][8][4];
#pragma unroll
    for (int mf = 0; mf < 2; mf++)
#pragma unroll
        for (int nf = 0; nf < 8; nf++)
#pragma unroll
            for (int r = 0; r < 4; r++) acc[mf][nf][r] = 0.f;

    g1_load_stage(smb, 0, m0, n0g, 0, M, tid);
    CP_COMMIT();

    // precomputed ldmatrix lane addressing
    int arow = lane & 15;
    int akoff = (lane >> 4) * 16;                       // bytes
    int brow = (lane & 7) | (((lane >> 4) & 1) << 3);
    int bkoff = ((lane >> 3) & 1) * 16;                 // bytes

    for (int c = 0; c < 16; c++) {
        if (c + 1 < 16) {
            g1_load_stage(smb, ((c + 1) & 1) * STAGE_B, m0, n0g, (c + 1) * 32, M, tid);
            CP_COMMIT();
            CP_WAIT(1);
        } else {
            CP_WAIT(0);
        }
        __syncthreads();

        uint32_t aB = smb + (c & 1) * STAGE_B;
        uint32_t bB = aB + 2 * TILE_B;

#pragma unroll
        for (int kf = 0; kf < 2; kf++) {
            uint32_t AH[2][4], AL[2][4];
#pragma unroll
            for (int mf = 0; mf < 2; mf++) {
                int R = mwarp * 32 + mf * 16;
                uint32_t ad = aB + (R + arow) * SST_B + kf * 32 + akoff;
                LDMX4(AH[mf], ad);
                LDMX4(AL[mf], ad + TILE_B);
            }
            uint32_t BH[4][4], BL[4][4];
#pragma unroll
            for (int nb = 0; nb < 4; nb++) {
                int Nn = nwarp * 64 + nb * 16;
                uint32_t bd = bB + (Nn + brow) * SST_B + kf * 32 + bkoff;
                LDMX4(BH[nb], bd);
                LDMX4(BL[nb], bd + TILE_B);
            }
#pragma unroll
            for (int mf = 0; mf < 2; mf++)
#pragma unroll
                for (int nf = 0; nf < 8; nf++) {
                    int nb = nf >> 1, h = (nf & 1) * 2;
                    MMA16816(acc[mf][nf], AH[mf], BH[nb][h], BH[nb][h + 1]);
                    MMA16816(acc[mf][nf], AH[mf], BL[nb][h], BL[nb][h + 1]);
                    MMA16816(acc[mf][nf], AL[mf], BH[nb][h], BH[nb][h + 1]);
                }
        }
        __syncthreads();
    }

    // epilogue: direct f32 stores
#pragma unroll
    for (int mf = 0; mf < 2; mf++) {
        int row = m0 + mwarp * 32 + mf * 16 + (lane >> 2);
#pragma unroll
        for (int nf = 0; nf < 8; nf++) {
            int col = n0g + nwarp * 64 + nf * 8 + (lane & 3) * 2;
            if (row < M)
                *(float2*)&g_h1[(size_t)row * F_H + col] =
                    make_float2(acc[mf][nf][0], acc[mf][nf][1]);
            if (row + 8 < M)
                *(float2*)&g_h1[(size_t)(row + 8) * F_H + col] =
                    make_float2(acc[mf][nf][2], acc[mf][nf][3]);
        }
    }
}

// ================= CSR aggregation layer 1 (fused bias+relu+self) =================
__global__ __launch_bounds__(64) void agg1_fused(const float* __restrict__ b1, int M) {
    int i = blockIdx.x;
    if (i >= M) return;
    int t = threadIdx.x;           // f4 column 0..63
    int lane = t & 31;
    int start = g_rowp[i], cnt = g_cnt[i];
    const float4* h1f = (const float4*)g_h1;
    float4 acc = make_float4(0.f, 0.f, 0.f, 0.f);
    for (int j = 0; j < cnt; j++) {
        int s = 0; float w = 0.f;
        if (lane == 0) { s = g_col[start + j]; w = g_dinv[s]; }
        s = __shfl_sync(0xffffffffu, s, 0);
        w = __shfl_sync(0xffffffffu, w, 0);
        float4 h = h1f[(size_t)s * 64 + t];
        acc.x = fmaf(w, h.x, acc.x);
        acc.y = fmaf(w, h.y, acc.y);
        acc.z = fmaf(w, h.z, acc.z);
        acc.w = fmaf(w, h.w, acc.w);
    }
    float di = g_dinv[i], d2 = di * di;
    float4 h = h1f[(size_t)i * 64 + t];
    float4 bb = ((const float4*)b1)[t];
    float4 o;
    o.x = fmaxf(fmaf(di, acc.x, fmaf(d2, h.x, bb.x)), 0.f);
    o.y = fmaxf(fmaf(di, acc.y, fmaf(d2, h.y, bb.y)), 0.f);
    o.z = fmaxf(fmaf(di, acc.z, fmaf(d2, h.z, bb.z)), 0.f);
    o.w = fmaxf(fmaf(di, acc.w, fmaf(d2, h.w, bb.w)), 0.f);
    ((float4*)g_agg1)[(size_t)i * 64 + t] = o;
}

// ================= GEMM2: h2[M,40] = agg1[M,256] @ W2[256,40] =================
__global__ __launch_bounds__(256) void gemm2(const float* __restrict__ W2, int M) {
    __shared__ float W2s[F_H * F_C];
    for (int i = threadIdx.x; i < F_H * F_C / 4; i += 256)
        ((float4*)W2s)[i] = ((const float4*)W2)[i];
    __syncthreads();
    int row = blockIdx.x * blockDim.x + threadIdx.x;
    if (row >= M) return;
    float4 acc[10];
#pragma unroll
    for (int c = 0; c < 10; c++) acc[c] = make_float4(0.f, 0.f, 0.f, 0.f);
    const float4* hr = (const float4*)&g_agg1[(size_t)row * F_H];
    for (int k4 = 0; k4 < F_H / 4; k4++) {
        float4 h = hr[k4];
        float hv[4] = {h.x, h.y, h.z, h.w};
#pragma unroll
        for (int kk = 0; kk < 4; kk++) {
            const float4* wrow = (const float4*)&W2s[(k4 * 4 + kk) * F_C];
#pragma unroll
            for (int c = 0; c < 10; c++) {
                float4 wv = wrow[c];
                acc[c].x = fmaf(hv[kk], wv.x, acc[c].x);
                acc[c].y = fmaf(hv[kk], wv.y, acc[c].y);
                acc[c].z = fmaf(hv[kk], wv.z, acc[c].z);
                acc[c].w = fmaf(hv[kk], wv.w, acc[c].w);
            }
        }
    }
    float4* out = (float4*)&g_h2[(size_t)row * F_C];
#pragma unroll
    for (int c = 0; c < 10; c++) out[c] = acc[c];
}

// ================= CSR aggregation layer 2 + log_softmax (fused) =================
__global__ __launch_bounds__(128) void agg2_fused(const float* __restrict__ b2,
                                                  float* __restrict__ out, int M) {
    int warp = threadIdx.x >> 5, lane = threadIdx.x & 31;
    int i = blockIdx.x * 4 + warp;
    if (i >= M) return;
    int start = g_rowp[i], cnt = g_cnt[i];
    const float4* h2f = (const float4*)g_h2;
    float4 acc = make_float4(0.f, 0.f, 0.f, 0.f);
    for (int j = 0; j < cnt; j++) {
        int s = 0; float w = 0.f;
        if (lane == 0) { s = g_col[start + j]; w = g_dinv[s]; }
        s = __shfl_sync(0xffffffffu, s, 0);
        w = __shfl_sync(0xffffffffu, w, 0);
        if (lane < 10) {
            float4 h = h2f[(size_t)s * 10 + lane];
            acc.x = fmaf(w, h.x, acc.x);
            acc.y = fmaf(w, h.y, acc.y);
            acc.z = fmaf(w, h.z, acc.z);
            acc.w = fmaf(w, h.w, acc.w);
        }
    }
    float di = g_dinv[i], d2 = di * di;
    float4 v = make_float4(0.f, 0.f, 0.f, 0.f);
    if (lane < 10) {
        float4 h = h2f[(size_t)i * 10 + lane];
        float4 bb = ((const float4*)b2)[lane];
        v.x = fmaf(di, acc.x, fmaf(d2, h.x, bb.x));
        v.y = fmaf(di, acc.y, fmaf(d2, h.y, bb.y));
        v.z = fmaf(di, acc.z, fmaf(d2, h.z, bb.z));
        v.w = fmaf(di, acc.w, fmaf(d2, h.w, bb.w));
    }
    float lm = (lane < 10) ? fmaxf(fmaxf(v.x, v.y), fmaxf(v.z, v.w)) : -3.4e38f;
#pragma unroll
    for (int o = 16; o; o >>= 1) lm = fmaxf(lm, __shfl_xor_sync(0xffffffffu, lm, o));
    float se = (lane < 10) ? (expf(v.x - lm) + expf(v.y - lm) + expf(v.z - lm) + expf(v.w - lm)) : 0.f;
#pragma unroll
    for (int o = 16; o; o >>= 1) se += __shfl_xor_sync(0xffffffffu, se, o);
    float ls = lm + logf(se);
    if (lane < 10) {
        float4 r = make_float4(v.x - ls, v.y - ls, v.z - ls, v.w - ls);
        ((float4*)&out[(size_t)i * F_C])[lane] = r;
    }
}

// ================= launch =================
extern "C" void kernel_launch(void* const* d_in, const int* in_sizes, int n_in,
                              void* d_out, int out_size) {
    const float* x  = (const float*)d_in[0];
    const float* W1 = (const float*)d_in[1];
    const float* b1 = (const float*)d_in[2];
    const float* W2 = (const float*)d_in[3];
    const float* b2 = (const float*)d_in[4];
    const void*  ei = d_in[5];

    int M = in_sizes[0] / F_IN;
    long long E = (long long)in_sizes[5] / 2;

    static int smem_set = 0;
    if (!smem_set) {
        cudaFuncSetAttribute(gemm1_mma, cudaFuncAttributeMaxDynamicSharedMemorySize, GEMM1_SMEM);
        smem_set = 1;
    }

    detect_dtype<<<1, 32>>>(ei);

    // CSR build + dinv
    zero_cnt<<<(M + 255) / 256, 256>>>(M);
    hist<<<(int)((E + 255) / 256), 256>>>(ei, E);
    int nb = (M + 255) / 256;
    scan1<<<nb, 256>>>(M);
    scan2<<<1, 512>>>(nb);
    scan3<<<nb, 256>>>(M);
    fill_csr<<<(int)((E + 255) / 256), 256>>>(ei, E);

    // bf16 splits
    long long n4 = (long long)M * F_IN / 4;
    split_x<<<(int)((n4 + 255) / 256), 256>>>(x, n4);
    split_w<<<(F_IN * F_H + 255) / 256, 256>>>(W1);

    // layer 1
    gemm1_mma<<<dim3((M + 127) / 128, 2), 256, GEMM1_SMEM>>>(M);
    agg1_fused<<<M, 64>>>(b1, M);

    // layer 2
    gemm2<<<(M + 255) / 256, 256>>>(W2, M);
    agg2_fused<<<(M + 3) / 4, 128>>>(b2, (float*)d_out, M);
}